// round 1
// baseline (speedup 1.0000x reference)
#include <cuda_runtime.h>
#include <math.h>
#include <stdint.h>

// Problem constants
#define BB   64
#define TT   256
#define DD   512
#define KK   2048
#define NN   16384   // BB*TT

// Output layout (pytree order: loss, quantized_st [B,D,T], perplexity, encoding_indices [N,1])
#define OUT_Q_OFF    1
#define OUT_PERP_OFF (1 + NN*DD)        // 8388609
#define OUT_IDX_OFF  (2 + NN*DD)        // 8388610

// Scratch (device globals: allocation-free per harness rules)
__device__ float  g_S[(size_t)NN * KK];        // full distance matrix, 512 MB
__device__ float  g_qscratch[(size_t)NN * DD]; // quantized rows [N, D], 33.5 MB
__device__ float  g_xsq[NN];
__device__ float  g_wsq[KK];
__device__ int    g_top3[NN * 3];
__device__ int    g_counts[KK];
__device__ double g_loss_sum;

// ---------------------------------------------------------------------------
__global__ void k_init() {
    int i = blockIdx.x * blockDim.x + threadIdx.x;
    if (i < KK) g_counts[i] = 0;
    if (i == 0) g_loss_sum = 0.0;
}

// ---------------------------------------------------------------------------
// blocks [0,64): xsq for batch b (one thread per t, coalesced along t)
// blocks [64,320): wsq, one warp per codebook row
__global__ void k_prep(const float* __restrict__ x, const float* __restrict__ W) {
    if (blockIdx.x < 64) {
        int b = blockIdx.x;
        int t = threadIdx.x;
        const float* p = x + (size_t)b * DD * TT + t;
        float s = 0.f;
        #pragma unroll 8
        for (int d = 0; d < DD; d++) {
            float v = p[(size_t)d * TT];
            s += v * v;
        }
        g_xsq[b * TT + t] = s;
    } else {
        int row  = (blockIdx.x - 64) * 8 + (threadIdx.x >> 5);
        int lane = threadIdx.x & 31;
        const float* p = W + (size_t)row * DD;
        float s = 0.f;
        #pragma unroll
        for (int j = lane; j < DD; j += 32) {
            float v = p[j];
            s += v * v;
        }
        #pragma unroll
        for (int off = 16; off; off >>= 1)
            s += __shfl_down_sync(0xffffffffu, s, off);
        if (lane == 0) g_wsq[row] = s;
    }
}

// ---------------------------------------------------------------------------
// Tiled fp32 GEMM: S[m,k] = fl( fl(xsq[m]+wsq[k]) - 2*(x_m . w_k) )
// Block tile 128x128, K-step 16, 256 threads, 8x8 micro-tile per thread.
// x is [B, D, T]: row m=(b,t), element d at x[b*D*T + d*T + t] (t contiguous).
__global__ __launch_bounds__(256, 2) void k_gemm(const float* __restrict__ x,
                                                 const float* __restrict__ W) {
    __shared__ float As[16][128];   // [d][t]
    __shared__ float Bs[16][128];   // [d][k]

    int tid = threadIdx.x;
    int rx = tid & 15;
    int ry = tid >> 4;
    int bx = blockIdx.x;            // column tile (k), 0..15
    int by = blockIdx.y;            // row tile (m), 0..127

    int b  = by >> 1;
    int t0 = (by & 1) * 128;
    const float* xbase = x + (size_t)b * DD * TT + t0;
    const float* wbase = W + (size_t)bx * 128 * DD;

    float acc[8][8];
    #pragma unroll
    for (int i = 0; i < 8; i++)
        #pragma unroll
        for (int j = 0; j < 8; j++) acc[i][j] = 0.f;

    for (int kt = 0; kt < DD; kt += 16) {
        __syncthreads();
        // Load A tile: 16 d-rows x 128 t (512 float4s, coalesced along t)
        #pragma unroll
        for (int l = 0; l < 2; l++) {
            int e  = tid + l * 256;
            int d  = e >> 5;
            int t4 = e & 31;
            float4 v = *reinterpret_cast<const float4*>(xbase + (size_t)(kt + d) * TT + t4 * 4);
            *reinterpret_cast<float4*>(&As[d][t4 * 4]) = v;
        }
        // Load B tile transposed: W rows -> Bs[d][k]
        #pragma unroll
        for (int l = 0; l < 2; l++) {
            int e  = tid + l * 256;
            int k  = e & 127;
            int d4 = e >> 7;
            float4 v = *reinterpret_cast<const float4*>(wbase + (size_t)k * DD + kt + d4 * 4);
            Bs[d4 * 4 + 0][k] = v.x;
            Bs[d4 * 4 + 1][k] = v.y;
            Bs[d4 * 4 + 2][k] = v.z;
            Bs[d4 * 4 + 3][k] = v.w;
        }
        __syncthreads();
        #pragma unroll
        for (int kk = 0; kk < 16; kk++) {
            float4 a0 = *reinterpret_cast<const float4*>(&As[kk][ry * 4]);
            float4 a1 = *reinterpret_cast<const float4*>(&As[kk][64 + ry * 4]);
            float4 b0 = *reinterpret_cast<const float4*>(&Bs[kk][rx * 4]);
            float4 b1 = *reinterpret_cast<const float4*>(&Bs[kk][64 + rx * 4]);
            float av[8] = {a0.x, a0.y, a0.z, a0.w, a1.x, a1.y, a1.z, a1.w};
            float bv[8] = {b0.x, b0.y, b0.z, b0.w, b1.x, b1.y, b1.z, b1.w};
            #pragma unroll
            for (int i = 0; i < 8; i++)
                #pragma unroll
                for (int j = 0; j < 8; j++)
                    acc[i][j] = fmaf(av[i], bv[j], acc[i][j]);
        }
    }

    // Epilogue: s = fl(fl(xsq+wsq) - 2*dot), mimicking reference rounding order
    int mrow[8], kcol[8];
    #pragma unroll
    for (int i = 0; i < 4; i++) { mrow[i] = ry * 4 + i; mrow[i + 4] = 64 + ry * 4 + i; }
    #pragma unroll
    for (int j = 0; j < 4; j++) { kcol[j] = rx * 4 + j; kcol[j + 4] = 64 + rx * 4 + j; }

    float xs[8], ws[8];
    #pragma unroll
    for (int i = 0; i < 8; i++) xs[i] = g_xsq[by * 128 + mrow[i]];
    #pragma unroll
    for (int j = 0; j < 8; j++) ws[j] = g_wsq[bx * 128 + kcol[j]];

    #pragma unroll
    for (int i = 0; i < 8; i++) {
        int m = by * 128 + mrow[i];
        float o[8];
        #pragma unroll
        for (int j = 0; j < 8; j++) {
            float tsum = __fadd_rn(xs[i], ws[j]);
            o[j] = __fadd_rn(tsum, -2.0f * acc[i][j]);
        }
        float* dst = &g_S[(size_t)m * KK + (size_t)bx * 128];
        *reinterpret_cast<float4*>(dst + rx * 4)      = make_float4(o[0], o[1], o[2], o[3]);
        *reinterpret_cast<float4*>(dst + 64 + rx * 4) = make_float4(o[4], o[5], o[6], o[7]);
    }
}

// ---------------------------------------------------------------------------
// Lexicographic (value, index) top-3: exactly matches jax.lax.top_k stability
__device__ __forceinline__ void ins3(float v, int i,
                                     float& v0, int& i0,
                                     float& v1, int& i1,
                                     float& v2, int& i2) {
    if (v < v0 || (v == v0 && i < i0)) {
        v2 = v1; i2 = i1; v1 = v0; i1 = i0; v0 = v; i0 = i;
    } else if (v < v1 || (v == v1 && i < i1)) {
        v2 = v1; i2 = i1; v1 = v; i1 = i;
    } else if (v < v2 || (v == v2 && i < i2)) {
        v2 = v; i2 = i;
    }
}

__global__ void k_top3() {
    int warp = threadIdx.x >> 5;
    int lane = threadIdx.x & 31;
    int n = blockIdx.x * 8 + warp;
    const float* srow = &g_S[(size_t)n * KK];

    float v0 = 3.402823466e38f, v1 = v0, v2 = v0;
    int   i0 = 0x7fffffff, i1 = i0, i2 = i0;

    #pragma unroll 4
    for (int k = lane; k < KK; k += 32) {
        float v = srow[k];
        ins3(v, k, v0, i0, v1, i1, v2, i2);
    }
    #pragma unroll
    for (int off = 16; off; off >>= 1) {
        float u0 = __shfl_down_sync(0xffffffffu, v0, off);
        int   j0 = __shfl_down_sync(0xffffffffu, i0, off);
        float u1 = __shfl_down_sync(0xffffffffu, v1, off);
        int   j1 = __shfl_down_sync(0xffffffffu, i1, off);
        float u2 = __shfl_down_sync(0xffffffffu, v2, off);
        int   j2 = __shfl_down_sync(0xffffffffu, i2, off);
        ins3(u0, j0, v0, i0, v1, i1, v2, i2);
        ins3(u1, j1, v0, i0, v1, i1, v2, i2);
        ins3(u2, j2, v0, i0, v1, i1, v2, i2);
    }
    if (lane == 0) {
        g_top3[n * 3 + 0] = i0;
        g_top3[n * 3 + 1] = i1;
        g_top3[n * 3 + 2] = i2;
    }
}

// ---------------------------------------------------------------------------
// quantized row = mean of 3 code rows (coalesced), + counts + index output
__global__ void k_quant(const float* __restrict__ W, float* __restrict__ out) {
    int n = blockIdx.x;
    int i0 = g_top3[n * 3 + 0];
    int i1 = g_top3[n * 3 + 1];
    int i2 = g_top3[n * 3 + 2];
    const float4* w0 = reinterpret_cast<const float4*>(W + (size_t)i0 * DD);
    const float4* w1 = reinterpret_cast<const float4*>(W + (size_t)i1 * DD);
    const float4* w2 = reinterpret_cast<const float4*>(W + (size_t)i2 * DD);
    float4* q = reinterpret_cast<float4*>(&g_qscratch[(size_t)n * DD]);

    int tid = threadIdx.x;  // 128 threads, D/4 = 128 float4s
    float4 a = w0[tid], b = w1[tid], c = w2[tid];
    float4 r;
    r.x = ((a.x + b.x) + c.x) / 3.0f;
    r.y = ((a.y + b.y) + c.y) / 3.0f;
    r.z = ((a.z + b.z) + c.z) / 3.0f;
    r.w = ((a.w + b.w) + c.w) / 3.0f;
    q[tid] = r;

    if (tid == 0) {
        atomicAdd(&g_counts[i0], 1);
        atomicAdd(&g_counts[i1], 1);
        atomicAdd(&g_counts[i2], 1);
        out[OUT_IDX_OFF + n] = (float)i2;   // encoding_indices = idx[:, RANK-1]
    }
}

// ---------------------------------------------------------------------------
// Transpose [N,D] -> [B,D,T] output + fused loss accumulation (all coalesced)
__global__ void k_trans(const float* __restrict__ x, float* __restrict__ out) {
    __shared__ float tile[32][33];
    __shared__ double red[8];
    int b  = blockIdx.z;
    int t0 = blockIdx.y * 32;
    int d0 = blockIdx.x * 32;
    int tx = threadIdx.x;   // 32
    int ty = threadIdx.y;   // 8

    #pragma unroll
    for (int i = 0; i < 4; i++) {
        int t = t0 + ty + i * 8;
        tile[ty + i * 8][tx] = g_qscratch[(size_t)(b * TT + t) * DD + d0 + tx];
    }
    __syncthreads();

    float lsum = 0.f;
    #pragma unroll
    for (int i = 0; i < 4; i++) {
        int d = d0 + ty + i * 8;
        int t = t0 + tx;
        float  q   = tile[tx][ty + i * 8];
        size_t off = (size_t)b * DD * TT + (size_t)d * TT + t;
        float  xv  = x[off];
        out[OUT_Q_OFF + off] = q;           // quantized_st == quantized numerically
        float df = q - xv;
        lsum += df * df;
    }
    #pragma unroll
    for (int off = 16; off; off >>= 1)
        lsum += __shfl_down_sync(0xffffffffu, lsum, off);
    if (tx == 0) red[ty] = (double)lsum;
    __syncthreads();
    if (tx == 0 && ty == 0) {
        double s = 0.0;
        #pragma unroll
        for (int i = 0; i < 8; i++) s += red[i];
        atomicAdd(&g_loss_sum, s);
    }
}

// ---------------------------------------------------------------------------
__global__ void k_final(float* __restrict__ out) {
    __shared__ float red[256];
    int tid = threadIdx.x;
    float local = 0.f;
    for (int k = tid; k < KK; k += 256) {
        float p = (float)g_counts[k] / 16384.0f;
        local += p * logf(p + 1e-10f);
    }
    red[tid] = local;
    __syncthreads();
    #pragma unroll
    for (int s = 128; s; s >>= 1) {
        if (tid < s) red[tid] += red[tid + s];
        __syncthreads();
    }
    if (tid == 0) {
        out[OUT_PERP_OFF] = expf(-red[0]);
        float m = (float)(g_loss_sum / (double)((size_t)NN * DD));
        out[0] = m + 0.25f * m;   // q_latent + COMMITMENT_COST * e_latent (identical means)
    }
}

// ---------------------------------------------------------------------------
extern "C" void kernel_launch(void* const* d_in, const int* in_sizes, int n_in,
                              void* d_out, int out_size) {
    const float* x = (const float*)d_in[0];
    const float* W = (const float*)d_in[1];
    // Defensive: detect swapped input order by element counts
    if (n_in >= 2 && in_sizes[0] == KK * DD && in_sizes[1] == BB * DD * TT) {
        const float* tmp = x; x = W; W = tmp;
    }
    float* out = (float*)d_out;
    (void)out_size;

    k_init <<<8, 256>>>();
    k_prep <<<320, 256>>>(x, W);
    k_gemm <<<dim3(16, 128), 256>>>(x, W);
    k_top3 <<<2048, 256>>>();
    k_quant<<<NN, 128>>>(W, out);
    k_trans<<<dim3(16, 8, 64), dim3(32, 8)>>>(x, out);
    k_final<<<1, 256>>>(out);
}

// round 7
// speedup vs baseline: 1.4956x; 1.4956x over previous
#include <cuda_runtime.h>
#include <cuda_bf16.h>
#include <math.h>
#include <stdint.h>

// Problem constants
#define BB   64
#define TT   256
#define DD   512
#define KK   2048
#define NN   16384   // BB*TT

// GEMM tiling
#define BM   128
#define BN   128
#define BKC  32
#define NKC  (DD / BKC)     // 16
#define APITCH_B 80         // bytes per SMEM row (32 bf16 = 64B, padded to 80)
#define DPITCH   129        // f32 per dist-tile row (bank-conflict-free row scan)
#define STAGE_BYTES 20480   // A(128*80) + B(128*80)
#define SMEM_TOTAL 66048    // max(2 stages = 40960, dist tile 128*129*4 = 66048)

// Output layout (pytree order: loss, quantized_st [B,D,T], perplexity, encoding_indices [N,1])
#define OUT_Q_OFF    1
#define OUT_PERP_OFF (1 + NN*DD)
#define OUT_IDX_OFF  (2 + NN*DD)

// ---------------------------------------------------------------------------
// Device scratch (allocation-free per harness rules)
__device__ __align__(128) __nv_bfloat16 g_A [(size_t)NN * DD];  // 16 MB, X rows bf16
__device__ __align__(128) __nv_bfloat16 g_Wb[(size_t)KK * DD];  //  2 MB, W rows bf16
__device__ __align__(128) float g_Xt[(size_t)NN * DD];          // 33.5 MB, X rows fp32
__device__ float  g_xsq[NN];
__device__ float  g_wsq[KK];
__device__ float  g_cv4[(size_t)NN * 16 * 4];   // per-(row, n-tile) approx top-4
__device__ int    g_ci4[(size_t)NN * 16 * 4];
__device__ int    g_c6 [(size_t)NN * 6];        // global approx top-6 candidates
__device__ int    g_top3[NN * 3];
__device__ float  g_qscratch[(size_t)NN * DD];
__device__ int    g_counts[KK];
__device__ double g_loss_sum;

// ---------------------------------------------------------------------------
__device__ __forceinline__ uint32_t s2u(const void* p) {
    uint32_t a;
    asm("{ .reg .u64 t; cvta.to.shared.u64 t, %1; cvt.u32.u64 %0, t; }" : "=r"(a) : "l"(p));
    return a;
}

#define CP_ASYNC16(dst, src) \
    asm volatile("cp.async.cg.shared.global [%0], [%1], 16;" :: "r"(dst), "l"(src))
#define CP_COMMIT asm volatile("cp.async.commit_group;" ::: "memory")
#define CP_WAIT1  asm volatile("cp.async.wait_group 1;" ::: "memory")
#define CP_WAIT0  asm volatile("cp.async.wait_group 0;" ::: "memory")

// ---------------------------------------------------------------------------
__global__ void k_init() {
    int i = blockIdx.x * blockDim.x + threadIdx.x;
    if (i < KK) g_counts[i] = 0;
    if (i == 0) g_loss_sum = 0.0;
}

// ---------------------------------------------------------------------------
// xsq per row (coalesced along t) + wsq per codebook row — exact fp32
__global__ void k_prep(const float* __restrict__ x, const float* __restrict__ W) {
    if (blockIdx.x < 64) {
        int b = blockIdx.x;
        int t = threadIdx.x;
        const float* p = x + (size_t)b * DD * TT + t;
        float s = 0.f;
        #pragma unroll 8
        for (int d = 0; d < DD; d++) { float v = p[(size_t)d * TT]; s += v * v; }
        g_xsq[b * TT + t] = s;
    } else {
        int row  = (blockIdx.x - 64) * 8 + (threadIdx.x >> 5);
        int lane = threadIdx.x & 31;
        const float* p = W + (size_t)row * DD;
        float s = 0.f;
        #pragma unroll
        for (int j = lane; j < DD; j += 32) { float v = p[j]; s += v * v; }
        #pragma unroll
        for (int off = 16; off; off >>= 1) s += __shfl_down_sync(0xffffffffu, s, off);
        if (lane == 0) g_wsq[row] = s;
    }
}

// ---------------------------------------------------------------------------
__global__ void k_split_w(const float* __restrict__ W) {
    int row = blockIdx.x;
    for (int d = threadIdx.x; d < DD; d += blockDim.x)
        g_Wb[(size_t)row * DD + d] = __float2bfloat16_rn(W[(size_t)row * DD + d]);
}

// ---------------------------------------------------------------------------
// Transpose x [B,D,T] -> rows [m][d]: fp32 copy (for rescore) + bf16 (for GEMM)
__global__ void k_split_x(const float* __restrict__ x) {
    __shared__ float tile[32][33];
    int b  = blockIdx.z;
    int t0 = blockIdx.y * 32;
    int d0 = blockIdx.x * 32;
    int tx = threadIdx.x, ty = threadIdx.y;  // 32 x 8

    #pragma unroll
    for (int j = 0; j < 4; j++) {
        int d = d0 + ty + 8 * j;
        tile[ty + 8 * j][tx] = x[(size_t)b * DD * TT + (size_t)d * TT + t0 + tx];
    }
    __syncthreads();
    #pragma unroll
    for (int j = 0; j < 4; j++) {
        int t = t0 + ty + 8 * j;
        size_t m = (size_t)b * TT + t;
        float v = tile[tx][ty + 8 * j];
        g_Xt[m * DD + d0 + tx] = v;
        g_A [m * DD + d0 + tx] = __float2bfloat16_rn(v);
    }
}

// ---------------------------------------------------------------------------
// insertion helpers (lexicographic (value, index); matches jax.lax.top_k order)
__device__ __forceinline__ void ins3(float v, int i,
                                     float& v0, int& i0, float& v1, int& i1,
                                     float& v2, int& i2) {
    if (v < v0 || (v == v0 && i < i0)) {
        v2 = v1; i2 = i1; v1 = v0; i1 = i0; v0 = v; i0 = i;
    } else if (v < v1 || (v == v1 && i < i1)) {
        v2 = v1; i2 = i1; v1 = v; i1 = i;
    } else if (v < v2 || (v == v2 && i < i2)) {
        v2 = v; i2 = i;
    }
}
__device__ __forceinline__ void insN(float v, int i, float* vs, int* is, int n) {
    if (v >= vs[n - 1]) return;
    int p = n - 1;
    while (p > 0 && v < vs[p - 1]) { vs[p] = vs[p - 1]; is[p] = is[p - 1]; p--; }
    vs[p] = v; is[p] = i;
}

// ---------------------------------------------------------------------------
// bf16 HMMA GEMM (approx -X.Wt dot products) + fused per-tile approx top-4.
// Block 128x128, 8 warps (2m x 4n), warp tile 64x32, K-chunk 32, 2-stage cp.async.
__global__ __launch_bounds__(256, 1) void k_gemm() {
    extern __shared__ char smem[];
    uint32_t sbase = s2u(smem);
    int tid = threadIdx.x, wid = tid >> 5, lane = tid & 31;
    int bx = blockIdx.x;            // n-tile 0..15
    int by = blockIdx.y;            // m-tile 0..127
    int m0 = by * BM, n0 = bx * BN;
    int wm = wid & 1, wn = wid >> 1;

    const __nv_bfloat16* Ag = g_A  + (size_t)m0 * DD;
    const __nv_bfloat16* Bg = g_Wb + (size_t)n0 * DD;

    float acc[4][4][4];
    #pragma unroll
    for (int i = 0; i < 4; i++)
        #pragma unroll
        for (int j = 0; j < 4; j++)
            #pragma unroll
            for (int r = 0; r < 4; r++) acc[i][j][r] = 0.f;

    // stage tile load: 512 A chunks + 512 B chunks of 16B, 4 per thread
    auto load_tile = [&](int stage, int kt) {
        uint32_t sA = sbase + stage * STAGE_BYTES;
        uint32_t sB = sA + BM * APITCH_B;
        #pragma unroll
        for (int r = 0; r < 4; r++) {
            int id = tid + r * 256;
            if (id < 512) {
                int row = id >> 2, c = id & 3;
                CP_ASYNC16(sA + row * APITCH_B + c * 16,
                           Ag + (size_t)row * DD + kt + c * 8);
            } else {
                int id2 = id - 512;
                int row = id2 >> 2, c = id2 & 3;
                CP_ASYNC16(sB + row * APITCH_B + c * 16,
                           Bg + (size_t)row * DD + kt + c * 8);
            }
        }
    };

    auto compute = [&](int stage) {
        uint32_t sA = sbase + stage * STAGE_BYTES;
        uint32_t sB = sA + BM * APITCH_B;
        #pragma unroll
        for (int ks = 0; ks < 2; ks++) {
            uint32_t a[4][4], b[4][2];
            #pragma unroll
            for (int mi = 0; mi < 4; mi++) {
                uint32_t row = wm * 64 + mi * 16 + (lane & 15);
                uint32_t col = ks * 16 + ((lane >> 4) << 3);
                uint32_t ad = sA + row * APITCH_B + col * 2;
                asm volatile("ldmatrix.sync.aligned.m8n8.x4.shared.b16 {%0,%1,%2,%3}, [%4];"
                    : "=r"(a[mi][0]), "=r"(a[mi][1]), "=r"(a[mi][2]), "=r"(a[mi][3])
                    : "r"(ad));
            }
            #pragma unroll
            for (int ni = 0; ni < 4; ni++) {
                int l2 = lane & 15;
                uint32_t n = wn * 32 + ni * 8 + (l2 & 7);
                uint32_t col = ks * 16 + ((l2 >> 3) << 3);
                uint32_t bd = sB + n * APITCH_B + col * 2;
                asm volatile("ldmatrix.sync.aligned.m8n8.x2.shared.b16 {%0,%1}, [%2];"
                    : "=r"(b[ni][0]), "=r"(b[ni][1]) : "r"(bd));
            }
            #pragma unroll
            for (int mi = 0; mi < 4; mi++)
                #pragma unroll
                for (int ni = 0; ni < 4; ni++) {
                    asm volatile(
                        "mma.sync.aligned.m16n8k16.row.col.f32.bf16.bf16.f32 "
                        "{%0,%1,%2,%3}, {%4,%5,%6,%7}, {%8,%9}, {%0,%1,%2,%3};"
                        : "+f"(acc[mi][ni][0]), "+f"(acc[mi][ni][1]),
                          "+f"(acc[mi][ni][2]), "+f"(acc[mi][ni][3])
                        : "r"(a[mi][0]), "r"(a[mi][1]), "r"(a[mi][2]), "r"(a[mi][3]),
                          "r"(b[ni][0]), "r"(b[ni][1]));
                }
        }
    };

    load_tile(0, 0); CP_COMMIT;
    for (int c = 0; c < NKC; c++) {
        if (c + 1 < NKC) { load_tile((c + 1) & 1, (c + 1) * BKC); CP_COMMIT; CP_WAIT1; }
        else             { CP_WAIT0; }
        __syncthreads();
        compute(c & 1);
        __syncthreads();
    }

    // Epilogue: dump dot products to SMEM dist tile, then per-row approx top-4
    float* dist = reinterpret_cast<float*>(smem);
    #pragma unroll
    for (int mi = 0; mi < 4; mi++)
        #pragma unroll
        for (int ni = 0; ni < 4; ni++) {
            int r0 = wm * 64 + mi * 16 + (lane >> 2);
            int c0 = wn * 32 + ni * 8 + 2 * (lane & 3);
            dist[r0 * DPITCH + c0]           = acc[mi][ni][0];
            dist[r0 * DPITCH + c0 + 1]       = acc[mi][ni][1];
            dist[(r0 + 8) * DPITCH + c0]     = acc[mi][ni][2];
            dist[(r0 + 8) * DPITCH + c0 + 1] = acc[mi][ni][3];
        }
    __syncthreads();

    if (tid < 128) {
        int r = tid, m = m0 + r;
        float xs = g_xsq[m];
        float vs[4] = {3.402823466e38f, 3.402823466e38f, 3.402823466e38f, 3.402823466e38f};
        int   is[4] = {0x7fffffff, 0x7fffffff, 0x7fffffff, 0x7fffffff};
        for (int j = 0; j < 128; j++) {
            float v = xs + g_wsq[n0 + j] - 2.0f * dist[r * DPITCH + j];
            insN(v, n0 + j, vs, is, 4);
        }
        size_t base = ((size_t)m * 16 + bx) * 4;
        #pragma unroll
        for (int s = 0; s < 4; s++) { g_cv4[base + s] = vs[s]; g_ci4[base + s] = is[s]; }
    }
}

// ---------------------------------------------------------------------------
// Merge 16 tiles x 4 candidates -> global approx top-6 per row
__global__ void k_merge() {
    int m = blockIdx.x * 256 + threadIdx.x;
    float vs[6]; int is[6];
    #pragma unroll
    for (int s = 0; s < 6; s++) { vs[s] = 3.402823466e38f; is[s] = 0x7fffffff; }
    size_t base = (size_t)m * 64;
    for (int c = 0; c < 64; c++) insN(g_cv4[base + c], g_ci4[base + c], vs, is, 6);
    #pragma unroll
    for (int s = 0; s < 6; s++) g_c6[(size_t)m * 6 + s] = is[s];
}

// ---------------------------------------------------------------------------
// Exact fp32 rescore of the 6 candidates; lexicographic top-3 (jax order).
// One warp per row; W (4MB) is L2-resident.
__global__ void k_rescore(const float* __restrict__ W) {
    int wid = threadIdx.x >> 5, lane = threadIdx.x & 31;
    int m = blockIdx.x * 8 + wid;

    const float4* xp = reinterpret_cast<const float4*>(g_Xt + (size_t)m * DD);
    float4 xv[4];
    #pragma unroll
    for (int i = 0; i < 4; i++) xv[i] = xp[lane + 32 * i];

    float xs = g_xsq[m];
    float v0 = 3.402823466e38f, v1 = v0, v2 = v0;
    int   i0 = 0x7fffffff, i1 = i0, i2 = i0;

    for (int c = 0; c < 6; c++) {
        int idx = g_c6[(size_t)m * 6 + c];
        const float4* wp = reinterpret_cast<const float4*>(W + (size_t)idx * DD);
        float s = 0.f;
        #pragma unroll
        for (int i = 0; i < 4; i++) {
            float4 wv = wp[lane + 32 * i];
            s = fmaf(xv[i].x, wv.x, s);
            s = fmaf(xv[i].y, wv.y, s);
            s = fmaf(xv[i].z, wv.z, s);
            s = fmaf(xv[i].w, wv.w, s);
        }
        #pragma unroll
        for (int off = 16; off; off >>= 1) s += __shfl_down_sync(0xffffffffu, s, off);
        if (lane == 0) {
            float dist = __fadd_rn(__fadd_rn(xs, g_wsq[idx]), -2.0f * s);
            ins3(dist, idx, v0, i0, v1, i1, v2, i2);
        }
    }
    if (lane == 0) {
        g_top3[m * 3 + 0] = i0;
        g_top3[m * 3 + 1] = i1;
        g_top3[m * 3 + 2] = i2;
    }
}

// ---------------------------------------------------------------------------
__global__ void k_quant(const float* __restrict__ W, float* __restrict__ out) {
    int n = blockIdx.x;
    int i0 = g_top3[n * 3 + 0];
    int i1 = g_top3[n * 3 + 1];
    int i2 = g_top3[n * 3 + 2];
    const float4* w0 = reinterpret_cast<const float4*>(W + (size_t)i0 * DD);
    const float4* w1 = reinterpret_cast<const float4*>(W + (size_t)i1 * DD);
    const float4* w2 = reinterpret_cast<const float4*>(W + (size_t)i2 * DD);
    float4* q = reinterpret_cast<float4*>(&g_qscratch[(size_t)n * DD]);

    int tid = threadIdx.x;
    float4 a = w0[tid], b = w1[tid], c = w2[tid];
    float4 r;
    r.x = ((a.x + b.x) + c.x) / 3.0f;
    r.y = ((a.y + b.y) + c.y) / 3.0f;
    r.z = ((a.z + b.z) + c.z) / 3.0f;
    r.w = ((a.w + b.w) + c.w) / 3.0f;
    q[tid] = r;

    if (tid == 0) {
        atomicAdd(&g_counts[i0], 1);
        atomicAdd(&g_counts[i1], 1);
        atomicAdd(&g_counts[i2], 1);
        out[OUT_IDX_OFF + n] = (float)i2;
    }
}

// ---------------------------------------------------------------------------
__global__ void k_trans(const float* __restrict__ x, float* __restrict__ out) {
    __shared__ float tile[32][33];
    __shared__ double red[8];
    int b  = blockIdx.z;
    int t0 = blockIdx.y * 32;
    int d0 = blockIdx.x * 32;
    int tx = threadIdx.x, ty = threadIdx.y;

    #pragma unroll
    for (int i = 0; i < 4; i++) {
        int t = t0 + ty + i * 8;
        tile[ty + i * 8][tx] = g_qscratch[(size_t)(b * TT + t) * DD + d0 + tx];
    }
    __syncthreads();

    float lsum = 0.f;
    #pragma unroll
    for (int i = 0; i < 4; i++) {
        int d = d0 + ty + i * 8;
        int t = t0 + tx;
        float  q   = tile[tx][ty + i * 8];
        size_t off = (size_t)b * DD * TT + (size_t)d * TT + t;
        float  xv  = x[off];
        out[OUT_Q_OFF + off] = q;
        float df = q - xv;
        lsum += df * df;
    }
    #pragma unroll
    for (int off = 16; off; off >>= 1)
        lsum += __shfl_down_sync(0xffffffffu, lsum, off);
    if (tx == 0) red[ty] = (double)lsum;
    __syncthreads();
    if (tx == 0 && ty == 0) {
        double s = 0.0;
        #pragma unroll
        for (int i = 0; i < 8; i++) s += red[i];
        atomicAdd(&g_loss_sum, s);
    }
}

// ---------------------------------------------------------------------------
__global__ void k_final(float* __restrict__ out) {
    __shared__ float red[256];
    int tid = threadIdx.x;
    float local = 0.f;
    for (int k = tid; k < KK; k += 256) {
        float p = (float)g_counts[k] / 16384.0f;
        local += p * logf(p + 1e-10f);
    }
    red[tid] = local;
    __syncthreads();
    #pragma unroll
    for (int s = 128; s; s >>= 1) {
        if (tid < s) red[tid] += red[tid + s];
        __syncthreads();
    }
    if (tid == 0) {
        out[OUT_PERP_OFF] = expf(-red[0]);
        float m = (float)(g_loss_sum / (double)((size_t)NN * DD));
        out[0] = m + 0.25f * m;
    }
}

// ---------------------------------------------------------------------------
extern "C" void kernel_launch(void* const* d_in, const int* in_sizes, int n_in,
                              void* d_out, int out_size) {
    const float* x = (const float*)d_in[0];
    const float* W = (const float*)d_in[1];
    if (n_in >= 2 && in_sizes[0] == KK * DD && in_sizes[1] == BB * DD * TT) {
        const float* tmp = x; x = W; W = tmp;
    }
    float* out = (float*)d_out;
    (void)out_size;

    cudaFuncSetAttribute(k_gemm, cudaFuncAttributeMaxDynamicSharedMemorySize,
                         SMEM_TOTAL);

    k_init   <<<8, 256>>>();
    k_prep   <<<320, 256>>>(x, W);
    k_split_w<<<KK, 256>>>(W);
    k_split_x<<<dim3(16, 8, 64), dim3(32, 8)>>>(x);
    k_gemm   <<<dim3(16, 128), 256, SMEM_TOTAL>>>();
    k_merge  <<<64, 256>>>();
    k_rescore<<<2048, 256>>>(W);
    k_quant  <<<NN, 128>>>(W, out);
    k_trans  <<<dim3(16, 8, 64), dim3(32, 8)>>>(x, out);
    k_final  <<<1, 256>>>(out);
}

// round 9
// speedup vs baseline: 1.6672x; 1.1147x over previous
#include <cuda_runtime.h>
#include <cuda_bf16.h>
#include <math.h>
#include <stdint.h>

// Problem constants
#define BB   64
#define TT   256
#define DD   512
#define KK   2048
#define NN   16384   // BB*TT

// GEMM tiling
#define BM   128
#define BN   128
#define BKC  64             // bf16 elements per K-chunk (128B per row)
#define NKC  (DD / BKC)     // 8
#define APITCH_B 144        // bytes per SMEM row (128B data + 16B pad; 9 mod 8 = 1 -> conflict-free)
#define DPITCH   129        // f32 per dist-tile row
#define STAGE_BYTES (256 * APITCH_B)   // A(128 rows) + B(128 rows) = 36864
#define NSTAGE 3
#define SMEM_TOTAL (NSTAGE * STAGE_BYTES)  // 110592 (dist tile 66048 fits inside)

// Output layout (pytree order: loss, quantized_st [B,D,T], perplexity, encoding_indices [N,1])
#define OUT_Q_OFF    1
#define OUT_PERP_OFF (1 + NN*DD)
#define OUT_IDX_OFF  (2 + NN*DD)

// ---------------------------------------------------------------------------
// Device scratch (allocation-free per harness rules)
__device__ __align__(128) __nv_bfloat16 g_A [(size_t)NN * DD];  // 16 MB
__device__ __align__(128) __nv_bfloat16 g_Wb[(size_t)KK * DD];  //  2 MB
__device__ __align__(128) float g_Xt[(size_t)NN * DD];          // 33.5 MB
__device__ float  g_xsq[NN];
__device__ float  g_wsq[KK];
__device__ float  g_cv4[(size_t)64 * NN];   // [c][m] layout, c = tile*4 + rank
__device__ int    g_ci4[(size_t)64 * NN];
__device__ int    g_c6 [(size_t)NN * 6];
__device__ int    g_top3[NN * 3];
__device__ int    g_counts[KK];
__device__ double g_loss_sum;

// ---------------------------------------------------------------------------
__device__ __forceinline__ uint32_t s2u(const void* p) {
    uint32_t a;
    asm("{ .reg .u64 t; cvta.to.shared.u64 t, %1; cvt.u32.u64 %0, t; }" : "=r"(a) : "l"(p));
    return a;
}

#define CP_ASYNC16(dst, src) \
    asm volatile("cp.async.cg.shared.global [%0], [%1], 16;" :: "r"(dst), "l"(src))
#define CP_COMMIT asm volatile("cp.async.commit_group;" ::: "memory")
#define CP_WAIT1  asm volatile("cp.async.wait_group 1;" ::: "memory")
#define CP_WAIT0  asm volatile("cp.async.wait_group 0;" ::: "memory")

// ---------------------------------------------------------------------------
__global__ void k_init() {
    int i = blockIdx.x * blockDim.x + threadIdx.x;
    if (i < KK) g_counts[i] = 0;
    if (i == 0) g_loss_sum = 0.0;
}

// ---------------------------------------------------------------------------
// xsq per row (sequential over d, coalesced along t) + wsq per codebook row.
// NUMERICS MUST STAY IDENTICAL: these values feed the exact rescore compare.
__global__ void k_prep(const float* __restrict__ x, const float* __restrict__ W) {
    if (blockIdx.x < 64) {
        int b = blockIdx.x;
        int t = threadIdx.x;
        const float* p = x + (size_t)b * DD * TT + t;
        float s = 0.f;
        #pragma unroll 8
        for (int d = 0; d < DD; d++) { float v = p[(size_t)d * TT]; s += v * v; }
        g_xsq[b * TT + t] = s;
    } else {
        int row  = (blockIdx.x - 64) * 8 + (threadIdx.x >> 5);
        int lane = threadIdx.x & 31;
        const float* p = W + (size_t)row * DD;
        float s = 0.f;
        #pragma unroll
        for (int j = lane; j < DD; j += 32) { float v = p[j]; s += v * v; }
        #pragma unroll
        for (int off = 16; off; off >>= 1) s += __shfl_down_sync(0xffffffffu, s, off);
        if (lane == 0) g_wsq[row] = s;
    }
}

// ---------------------------------------------------------------------------
// Elementwise W -> bf16
__global__ void k_split_w(const float* __restrict__ W) {
    int i = blockIdx.x * 256 + threadIdx.x;   // KK*DD = 1M elements
    g_Wb[i] = __float2bfloat16_rn(W[i]);
}

// ---------------------------------------------------------------------------
// Transpose x [B,D,T] -> rows [m][d]: fp32 copy (for rescore) + bf16 (for GEMM)
__global__ void k_split_x(const float* __restrict__ x) {
    __shared__ float tile[32][33];
    int b  = blockIdx.z;
    int t0 = blockIdx.y * 32;
    int d0 = blockIdx.x * 32;
    int tx = threadIdx.x, ty = threadIdx.y;  // 32 x 8

    #pragma unroll
    for (int j = 0; j < 4; j++) {
        int d = d0 + ty + 8 * j;
        tile[ty + 8 * j][tx] = x[(size_t)b * DD * TT + (size_t)d * TT + t0 + tx];
    }
    __syncthreads();
    #pragma unroll
    for (int j = 0; j < 4; j++) {
        int t = t0 + ty + 8 * j;
        size_t m = (size_t)b * TT + t;
        float v = tile[tx][ty + 8 * j];
        g_Xt[m * DD + d0 + tx] = v;
        g_A [m * DD + d0 + tx] = __float2bfloat16_rn(v);
    }
}

// ---------------------------------------------------------------------------
// insertion helpers (lexicographic (value, index); matches jax.lax.top_k order)
__device__ __forceinline__ void ins3(float v, int i,
                                     float& v0, int& i0, float& v1, int& i1,
                                     float& v2, int& i2) {
    if (v < v0 || (v == v0 && i < i0)) {
        v2 = v1; i2 = i1; v1 = v0; i1 = i0; v0 = v; i0 = i;
    } else if (v < v1 || (v == v1 && i < i1)) {
        v2 = v1; i2 = i1; v1 = v; i1 = i;
    } else if (v < v2 || (v == v2 && i < i2)) {
        v2 = v; i2 = i;
    }
}
__device__ __forceinline__ void insN(float v, int i, float* vs, int* is, int n) {
    if (v >= vs[n - 1]) return;
    int p = n - 1;
    while (p > 0 && v < vs[p - 1]) { vs[p] = vs[p - 1]; is[p] = is[p - 1]; p--; }
    vs[p] = v; is[p] = i;
}

// ---------------------------------------------------------------------------
// bf16 HMMA GEMM (approx -X.Wt dot products) + fused per-tile approx top-4.
// Block 128x128, 8 warps (2m x 4n), warp tile 64x32, K-chunk 64, 3-stage
// cp.async pipeline with ONE __syncthreads per chunk.
__global__ __launch_bounds__(256, 1) void k_gemm() {
    extern __shared__ char smem[];
    uint32_t sbase = s2u(smem);
    int tid = threadIdx.x, wid = tid >> 5, lane = tid & 31;
    int bx = blockIdx.x;            // n-tile 0..15
    int by = blockIdx.y;            // m-tile 0..127
    int m0 = by * BM, n0 = bx * BN;
    int wm = wid & 1, wn = wid >> 1;

    const __nv_bfloat16* Ag = g_A  + (size_t)m0 * DD;
    const __nv_bfloat16* Bg = g_Wb + (size_t)n0 * DD;

    float acc[4][4][4];
    #pragma unroll
    for (int i = 0; i < 4; i++)
        #pragma unroll
        for (int j = 0; j < 4; j++)
            #pragma unroll
            for (int r = 0; r < 4; r++) acc[i][j][r] = 0.f;

    // chunk loader: 2048 x 16B cp.async, 8 per thread
    auto load_tile = [&](int stage, int kt) {
        uint32_t sA = sbase + stage * STAGE_BYTES;
        uint32_t sB = sA + BM * APITCH_B;
        #pragma unroll
        for (int r = 0; r < 8; r++) {
            int id  = tid + r * 256;
            int row = (id >> 3) & 127;
            int c   = id & 7;
            if (id < 1024)
                CP_ASYNC16(sA + row * APITCH_B + c * 16,
                           Ag + (size_t)row * DD + kt + c * 8);
            else
                CP_ASYNC16(sB + row * APITCH_B + c * 16,
                           Bg + (size_t)row * DD + kt + c * 8);
        }
    };

    auto compute = [&](int stage) {
        uint32_t sA = sbase + stage * STAGE_BYTES;
        uint32_t sB = sA + BM * APITCH_B;
        #pragma unroll
        for (int ks = 0; ks < 4; ks++) {
            uint32_t a[4][4], b[4][2];
            #pragma unroll
            for (int mi = 0; mi < 4; mi++) {
                uint32_t row = wm * 64 + mi * 16 + (lane & 15);
                uint32_t ad  = sA + row * APITCH_B + ks * 32 + ((lane >> 4) << 4);
                asm volatile("ldmatrix.sync.aligned.m8n8.x4.shared.b16 {%0,%1,%2,%3}, [%4];"
                    : "=r"(a[mi][0]), "=r"(a[mi][1]), "=r"(a[mi][2]), "=r"(a[mi][3])
                    : "r"(ad));
            }
            #pragma unroll
            for (int ni = 0; ni < 4; ni++) {
                int l2 = lane & 15;
                uint32_t n  = wn * 32 + ni * 8 + (l2 & 7);
                uint32_t bd = sB + n * APITCH_B + ks * 32 + ((l2 >> 3) << 4);
                asm volatile("ldmatrix.sync.aligned.m8n8.x2.shared.b16 {%0,%1}, [%2];"
                    : "=r"(b[ni][0]), "=r"(b[ni][1]) : "r"(bd));
            }
            #pragma unroll
            for (int mi = 0; mi < 4; mi++)
                #pragma unroll
                for (int ni = 0; ni < 4; ni++) {
                    asm volatile(
                        "mma.sync.aligned.m16n8k16.row.col.f32.bf16.bf16.f32 "
                        "{%0,%1,%2,%3}, {%4,%5,%6,%7}, {%8,%9}, {%0,%1,%2,%3};"
                        : "+f"(acc[mi][ni][0]), "+f"(acc[mi][ni][1]),
                          "+f"(acc[mi][ni][2]), "+f"(acc[mi][ni][3])
                        : "r"(a[mi][0]), "r"(a[mi][1]), "r"(a[mi][2]), "r"(a[mi][3]),
                          "r"(b[ni][0]), "r"(b[ni][1]));
                }
        }
    };

    load_tile(0, 0); CP_COMMIT;
    load_tile(1, BKC); CP_COMMIT;
    for (int c = 0; c < NKC; c++) {
        if (c == NKC - 1) { CP_WAIT0; } else { CP_WAIT1; }
        __syncthreads();   // chunk c resident; everyone past compute(c-1)
        if (c + 2 < NKC) { load_tile((c + 2) % NSTAGE, (c + 2) * BKC); CP_COMMIT; }
        compute(c % NSTAGE);
    }
    __syncthreads();       // all compute done before smem reuse

    // Epilogue: dump dot products to SMEM dist tile
    float* dist = reinterpret_cast<float*>(smem);
    #pragma unroll
    for (int mi = 0; mi < 4; mi++)
        #pragma unroll
        for (int ni = 0; ni < 4; ni++) {
            int r0 = wm * 64 + mi * 16 + (lane >> 2);
            int c0 = wn * 32 + ni * 8 + 2 * (lane & 3);
            dist[r0 * DPITCH + c0]           = acc[mi][ni][0];
            dist[r0 * DPITCH + c0 + 1]       = acc[mi][ni][1];
            dist[(r0 + 8) * DPITCH + c0]     = acc[mi][ni][2];
            dist[(r0 + 8) * DPITCH + c0 + 1] = acc[mi][ni][3];
        }
    __syncthreads();

    // Approx top-4 per row: 2 threads/row scan 64 cols each, shfl pair-merge.
    // (Row-constant xsq omitted: rank-invariant; exact rescore fixes values.)
    {
        int r = tid >> 1, h = tid & 1, m = m0 + r;
        float vs[4] = {3.402823466e38f, 3.402823466e38f, 3.402823466e38f, 3.402823466e38f};
        int   is[4] = {0x7fffffff, 0x7fffffff, 0x7fffffff, 0x7fffffff};
        const float* dr = dist + r * DPITCH + h * 64;
        int nb = n0 + h * 64;
        #pragma unroll 4
        for (int j = 0; j < 64; j++) {
            float v = g_wsq[nb + j] - 2.0f * dr[j];
            insN(v, nb + j, vs, is, 4);
        }
        float ov[4]; int oi[4];
        #pragma unroll
        for (int s = 0; s < 4; s++) { ov[s] = vs[s]; oi[s] = is[s]; }
        #pragma unroll
        for (int s = 0; s < 4; s++) {
            float pv = __shfl_xor_sync(0xffffffffu, ov[s], 1);
            int   pi = __shfl_xor_sync(0xffffffffu, oi[s], 1);
            insN(pv, pi, vs, is, 4);
        }
        if (h == 0) {
            #pragma unroll
            for (int s = 0; s < 4; s++) {
                g_cv4[(size_t)(bx * 4 + s) * NN + m] = vs[s];
                g_ci4[(size_t)(bx * 4 + s) * NN + m] = is[s];
            }
        }
    }
}

// ---------------------------------------------------------------------------
// Merge 16 tiles x 4 candidates -> global approx top-6 per row (coalesced)
__global__ void k_merge() {
    int m = blockIdx.x * 256 + threadIdx.x;
    float vs[6]; int is[6];
    #pragma unroll
    for (int s = 0; s < 6; s++) { vs[s] = 3.402823466e38f; is[s] = 0x7fffffff; }
    for (int c = 0; c < 64; c++)
        insN(g_cv4[(size_t)c * NN + m], g_ci4[(size_t)c * NN + m], vs, is, 6);
    #pragma unroll
    for (int s = 0; s < 6; s++) g_c6[(size_t)m * 6 + s] = is[s];
}

// ---------------------------------------------------------------------------
// Exact fp32 rescore (identical numerics to prior passing rounds) + counts/idx
__global__ void k_rescore(const float* __restrict__ W, float* __restrict__ out) {
    int wid = threadIdx.x >> 5, lane = threadIdx.x & 31;
    int m = blockIdx.x * 8 + wid;

    const float4* xp = reinterpret_cast<const float4*>(g_Xt + (size_t)m * DD);
    float4 xv[4];
    #pragma unroll
    for (int i = 0; i < 4; i++) xv[i] = xp[lane + 32 * i];

    float xs = g_xsq[m];
    float v0 = 3.402823466e38f, v1 = v0, v2 = v0;
    int   i0 = 0x7fffffff, i1 = i0, i2 = i0;

    for (int c = 0; c < 6; c++) {
        int idx = g_c6[(size_t)m * 6 + c];
        const float4* wp = reinterpret_cast<const float4*>(W + (size_t)idx * DD);
        float s = 0.f;
        #pragma unroll
        for (int i = 0; i < 4; i++) {
            float4 wv = wp[lane + 32 * i];
            s = fmaf(xv[i].x, wv.x, s);
            s = fmaf(xv[i].y, wv.y, s);
            s = fmaf(xv[i].z, wv.z, s);
            s = fmaf(xv[i].w, wv.w, s);
        }
        #pragma unroll
        for (int off = 16; off; off >>= 1) s += __shfl_down_sync(0xffffffffu, s, off);
        if (lane == 0) {
            float dist = __fadd_rn(__fadd_rn(xs, g_wsq[idx]), -2.0f * s);
            ins3(dist, idx, v0, i0, v1, i1, v2, i2);
        }
    }
    if (lane == 0) {
        g_top3[m * 3 + 0] = i0;
        g_top3[m * 3 + 1] = i1;
        g_top3[m * 3 + 2] = i2;
        atomicAdd(&g_counts[i0], 1);
        atomicAdd(&g_counts[i1], 1);
        atomicAdd(&g_counts[i2], 1);
        out[OUT_IDX_OFF + m] = (float)i2;
    }
}

// ---------------------------------------------------------------------------
// Fused quantize + transpose + loss: gathers W rows directly (L2/L1-resident),
// writes out[B,D,T] coalesced. Same value math/order as the old quant+trans.
__global__ void k_out(const float* __restrict__ x, const float* __restrict__ W,
                      float* __restrict__ out) {
    __shared__ double red[8];
    int b  = blockIdx.z;
    int t0 = blockIdx.y * 32;
    int d0 = blockIdx.x * 32;
    int tx = threadIdx.x, ty = threadIdx.y;   // 32 x 8

    int m = b * TT + t0 + tx;
    int j0 = g_top3[m * 3 + 0];
    int j1 = g_top3[m * 3 + 1];
    int j2 = g_top3[m * 3 + 2];
    const float* w0 = W + (size_t)j0 * DD;
    const float* w1 = W + (size_t)j1 * DD;
    const float* w2 = W + (size_t)j2 * DD;

    float lsum = 0.f;
    #pragma unroll
    for (int i = 0; i < 4; i++) {
        int d = d0 + ty + 8 * i;
        float q = ((w0[d] + w1[d]) + w2[d]) / 3.0f;
        size_t off = (size_t)b * DD * TT + (size_t)d * TT + t0 + tx;
        float xv = x[off];
        out[OUT_Q_OFF + off] = q;
        float df = q - xv;
        lsum += df * df;
    }
    #pragma unroll
    for (int off = 16; off; off >>= 1)
        lsum += __shfl_down_sync(0xffffffffu, lsum, off);
    if (tx == 0) red[ty] = (double)lsum;
    __syncthreads();
    if (tx == 0 && ty == 0) {
        double s = 0.0;
        #pragma unroll
        for (int i = 0; i < 8; i++) s += red[i];
        atomicAdd(&g_loss_sum, s);
    }
}

// ---------------------------------------------------------------------------
__global__ void k_final(float* __restrict__ out) {
    __shared__ float red[256];
    int tid = threadIdx.x;
    float local = 0.f;
    for (int k = tid; k < KK; k += 256) {
        float p = (float)g_counts[k] / 16384.0f;
        local += p * logf(p + 1e-10f);
    }
    red[tid] = local;
    __syncthreads();
    #pragma unroll
    for (int s = 128; s; s >>= 1) {
        if (tid < s) red[tid] += red[tid + s];
        __syncthreads();
    }
    if (tid == 0) {
        out[OUT_PERP_OFF] = expf(-red[0]);
        float m = (float)(g_loss_sum / (double)((size_t)NN * DD));
        out[0] = m + 0.25f * m;
    }
}

// ---------------------------------------------------------------------------
extern "C" void kernel_launch(void* const* d_in, const int* in_sizes, int n_in,
                              void* d_out, int out_size) {
    const float* x = (const float*)d_in[0];
    const float* W = (const float*)d_in[1];
    if (n_in >= 2 && in_sizes[0] == KK * DD && in_sizes[1] == BB * DD * TT) {
        const float* tmp = x; x = W; W = tmp;
    }
    float* out = (float*)d_out;
    (void)out_size;

    cudaFuncSetAttribute(k_gemm, cudaFuncAttributeMaxDynamicSharedMemorySize,
                         SMEM_TOTAL);

    k_init   <<<8, 256>>>();
    k_prep   <<<320, 256>>>(x, W);
    k_split_w<<<(KK * DD) / 256, 256>>>(W);
    k_split_x<<<dim3(16, 8, 64), dim3(32, 8)>>>(x);
    k_gemm   <<<dim3(16, 128), 256, SMEM_TOTAL>>>();
    k_merge  <<<64, 256>>>();
    k_rescore<<<2048, 256>>>(W, out);
    k_out    <<<dim3(16, 8, 64), dim3(32, 8)>>>(x, W, out);
    k_final  <<<1, 256>>>(out);
}

// round 11
// speedup vs baseline: 1.6813x; 1.0085x over previous
#include <cuda_runtime.h>
#include <cuda_bf16.h>
#include <math.h>
#include <stdint.h>

// Problem constants
#define BB   64
#define TT   256
#define DD   512
#define KK   2048
#define NN   16384   // BB*TT

// GEMM tiling
#define BM   128
#define BN   256
#define BKC  64             // bf16 elements per K-chunk (128B per row)
#define NKC  (DD / BKC)     // 8
#define APITCH_B 144        // 128B data + 16B pad (conflict-free ldmatrix)
#define DPITCH   257        // f32 per dist-tile row (257 mod 32 = 1)
#define STAGE_BYTES ((BM + BN) * APITCH_B)   // 384*144 = 55296
#define NSTAGE 2
#define SMEM_GEMM (NSTAGE * STAGE_BYTES)     // 110592
#define SMEM_DIST (BM * DPITCH * 4)          // 131584
#define SMEM_TOTAL SMEM_DIST                 // max(110592, 131584)

#define NTILE (KK / BN)     // 8
#define CPT   6             // candidates kept per (row, n-tile)
#define NCAND (NTILE * CPT) // 48

// Output layout (pytree order: loss, quantized_st [B,D,T], perplexity, encoding_indices [N,1])
#define OUT_Q_OFF    1
#define OUT_PERP_OFF (1 + NN*DD)
#define OUT_IDX_OFF  (2 + NN*DD)

// ---------------------------------------------------------------------------
// Device scratch (allocation-free per harness rules)
__device__ __align__(128) __nv_bfloat16 g_A [(size_t)NN * DD];  // 16 MB
__device__ __align__(128) __nv_bfloat16 g_Wb[(size_t)KK * DD];  //  2 MB
__device__ __align__(128) float g_Xt[(size_t)NN * DD];          // 33.5 MB
__device__ float  g_xsq[NN];
__device__ float  g_wsq[KK];
__device__ float  g_cv[(size_t)NCAND * NN];   // [c][m] layout
__device__ int    g_ci[(size_t)NCAND * NN];
__device__ int    g_c6 [(size_t)NN * 6];
__device__ int    g_top3[NN * 3];
__device__ int    g_counts[KK];
__device__ double g_loss_sum;

// ---------------------------------------------------------------------------
__device__ __forceinline__ uint32_t s2u(const void* p) {
    uint32_t a;
    asm("{ .reg .u64 t; cvta.to.shared.u64 t, %1; cvt.u32.u64 %0, t; }" : "=r"(a) : "l"(p));
    return a;
}

#define CP_ASYNC16(dst, src) \
    asm volatile("cp.async.cg.shared.global [%0], [%1], 16;" :: "r"(dst), "l"(src))
#define CP_COMMIT asm volatile("cp.async.commit_group;" ::: "memory")
#define CP_WAIT0  asm volatile("cp.async.wait_group 0;" ::: "memory")

// ---------------------------------------------------------------------------
__global__ void k_init() {
    int i = blockIdx.x * blockDim.x + threadIdx.x;
    if (i < KK) g_counts[i] = 0;
    if (i == 0) g_loss_sum = 0.0;
}

// ---------------------------------------------------------------------------
// xsq per row (sequential over d, coalesced along t) + wsq per codebook row.
// NUMERICS MUST STAY IDENTICAL: these values feed the exact rescore compare.
__global__ void k_prep(const float* __restrict__ x, const float* __restrict__ W) {
    if (blockIdx.x < 64) {
        int b = blockIdx.x;
        int t = threadIdx.x;
        const float* p = x + (size_t)b * DD * TT + t;
        float s = 0.f;
        #pragma unroll 8
        for (int d = 0; d < DD; d++) { float v = p[(size_t)d * TT]; s += v * v; }
        g_xsq[b * TT + t] = s;
    } else {
        int row  = (blockIdx.x - 64) * 8 + (threadIdx.x >> 5);
        int lane = threadIdx.x & 31;
        const float* p = W + (size_t)row * DD;
        float s = 0.f;
        #pragma unroll
        for (int j = lane; j < DD; j += 32) { float v = p[j]; s += v * v; }
        #pragma unroll
        for (int off = 16; off; off >>= 1) s += __shfl_down_sync(0xffffffffu, s, off);
        if (lane == 0) g_wsq[row] = s;
    }
}

// ---------------------------------------------------------------------------
__global__ void k_split_w(const float* __restrict__ W) {
    int i = blockIdx.x * 256 + threadIdx.x;
    g_Wb[i] = __float2bfloat16_rn(W[i]);
}

// ---------------------------------------------------------------------------
// Transpose x [B,D,T] -> rows [m][d]: fp32 copy (for rescore) + bf16 (for GEMM)
__global__ void k_split_x(const float* __restrict__ x) {
    __shared__ float tile[32][33];
    int b  = blockIdx.z;
    int t0 = blockIdx.y * 32;
    int d0 = blockIdx.x * 32;
    int tx = threadIdx.x, ty = threadIdx.y;  // 32 x 8

    #pragma unroll
    for (int j = 0; j < 4; j++) {
        int d = d0 + ty + 8 * j;
        tile[ty + 8 * j][tx] = x[(size_t)b * DD * TT + (size_t)d * TT + t0 + tx];
    }
    __syncthreads();
    #pragma unroll
    for (int j = 0; j < 4; j++) {
        int t = t0 + ty + 8 * j;
        size_t m = (size_t)b * TT + t;
        float v = tile[tx][ty + 8 * j];
        g_Xt[m * DD + d0 + tx] = v;
        g_A [m * DD + d0 + tx] = __float2bfloat16_rn(v);
    }
}

// ---------------------------------------------------------------------------
// insertion helpers (lexicographic (value, index); matches jax.lax.top_k order)
__device__ __forceinline__ void ins3(float v, int i,
                                     float& v0, int& i0, float& v1, int& i1,
                                     float& v2, int& i2) {
    if (v < v0 || (v == v0 && i < i0)) {
        v2 = v1; i2 = i1; v1 = v0; i1 = i0; v0 = v; i0 = i;
    } else if (v < v1 || (v == v1 && i < i1)) {
        v2 = v1; i2 = i1; v1 = v; i1 = i;
    } else if (v < v2 || (v == v2 && i < i2)) {
        v2 = v; i2 = i;
    }
}
__device__ __forceinline__ void insN(float v, int i, float* vs, int* is, int n) {
    if (v >= vs[n - 1]) return;
    int p = n - 1;
    while (p > 0 && v < vs[p - 1]) { vs[p] = vs[p - 1]; is[p] = is[p - 1]; p--; }
    vs[p] = v; is[p] = i;
}

// ---------------------------------------------------------------------------
// bf16 HMMA GEMM (approx -X.Wt dot products) + fused per-tile approx top-6.
// Block 128x256, 8 warps (2m x 4n), warp tile 64x64, K-chunk 64, 2-stage
// cp.async pipeline with ONE __syncthreads per chunk. All-x4 ldmatrix.
__global__ __launch_bounds__(256, 1) void k_gemm() {
    extern __shared__ char smem[];
    uint32_t sbase = s2u(smem);
    int tid = threadIdx.x, wid = tid >> 5, lane = tid & 31;
    int bx = blockIdx.x;            // n-tile 0..7
    int by = blockIdx.y;            // m-tile 0..127
    int m0 = by * BM, n0 = bx * BN;
    int wm = wid & 1, wn = wid >> 1;

    const __nv_bfloat16* Ag = g_A  + (size_t)m0 * DD;
    const __nv_bfloat16* Bg = g_Wb + (size_t)n0 * DD;

    float acc[4][8][4];
    #pragma unroll
    for (int i = 0; i < 4; i++)
        #pragma unroll
        for (int j = 0; j < 8; j++)
            #pragma unroll
            for (int r = 0; r < 4; r++) acc[i][j][r] = 0.f;

    // chunk loader: (128 A + 256 B) rows x 8 x 16B = 3072 cp.async, 12/thread
    auto load_tile = [&](int stage, int kt) {
        uint32_t sA = sbase + stage * STAGE_BYTES;
        uint32_t sB = sA + BM * APITCH_B;
        #pragma unroll
        for (int r = 0; r < 12; r++) {
            int id = tid + r * 256;
            if (id < 1024) {
                int row = id >> 3, c = id & 7;
                CP_ASYNC16(sA + row * APITCH_B + c * 16,
                           Ag + (size_t)row * DD + kt + c * 8);
            } else {
                int id2 = id - 1024;
                int row = id2 >> 3, c = id2 & 7;
                CP_ASYNC16(sB + row * APITCH_B + c * 16,
                           Bg + (size_t)row * DD + kt + c * 8);
            }
        }
    };

    auto compute = [&](int stage) {
        uint32_t sA = sbase + stage * STAGE_BYTES;
        uint32_t sB = sA + BM * APITCH_B;
        #pragma unroll
        for (int ks = 0; ks < 4; ks++) {
            uint32_t a[4][4], b[8][2];
            #pragma unroll
            for (int mi = 0; mi < 4; mi++) {
                uint32_t row = wm * 64 + mi * 16 + (lane & 15);
                uint32_t ad  = sA + row * APITCH_B + ks * 32 + ((lane >> 4) << 4);
                asm volatile("ldmatrix.sync.aligned.m8n8.x4.shared.b16 {%0,%1,%2,%3}, [%4];"
                    : "=r"(a[mi][0]), "=r"(a[mi][1]), "=r"(a[mi][2]), "=r"(a[mi][3])
                    : "r"(ad));
            }
            #pragma unroll
            for (int nj = 0; nj < 4; nj++) {
                // x4 covers two n-groups of 8: rows n..n+7 (regs 0,1) and n+8..n+15 (regs 2,3)
                uint32_t n  = wn * 64 + nj * 16 + ((lane >> 4) << 3) + (lane & 7);
                uint32_t bd = sB + n * APITCH_B + ks * 32 + (((lane >> 3) & 1) << 4);
                asm volatile("ldmatrix.sync.aligned.m8n8.x4.shared.b16 {%0,%1,%2,%3}, [%4];"
                    : "=r"(b[2 * nj][0]), "=r"(b[2 * nj][1]),
                      "=r"(b[2 * nj + 1][0]), "=r"(b[2 * nj + 1][1])
                    : "r"(bd));
            }
            #pragma unroll
            for (int mi = 0; mi < 4; mi++)
                #pragma unroll
                for (int ni = 0; ni < 8; ni++) {
                    asm volatile(
                        "mma.sync.aligned.m16n8k16.row.col.f32.bf16.bf16.f32 "
                        "{%0,%1,%2,%3}, {%4,%5,%6,%7}, {%8,%9}, {%0,%1,%2,%3};"
                        : "+f"(acc[mi][ni][0]), "+f"(acc[mi][ni][1]),
                          "+f"(acc[mi][ni][2]), "+f"(acc[mi][ni][3])
                        : "r"(a[mi][0]), "r"(a[mi][1]), "r"(a[mi][2]), "r"(a[mi][3]),
                          "r"(b[ni][0]), "r"(b[ni][1]));
                }
        }
    };

    load_tile(0, 0); CP_COMMIT;
    for (int c = 0; c < NKC; c++) {
        CP_WAIT0;
        __syncthreads();   // chunk c resident; all threads past compute(c-1)
        if (c + 1 < NKC) { load_tile((c + 1) & 1, (c + 1) * BKC); CP_COMMIT; }
        compute(c & 1);
    }
    __syncthreads();       // all compute done before smem reuse

    // Epilogue: dump dot products to SMEM dist tile
    float* dist = reinterpret_cast<float*>(smem);
    #pragma unroll
    for (int mi = 0; mi < 4; mi++)
        #pragma unroll
        for (int ni = 0; ni < 8; ni++) {
            int r0 = wm * 64 + mi * 16 + (lane >> 2);
            int c0 = wn * 64 + ni * 8 + 2 * (lane & 3);
            dist[r0 * DPITCH + c0]           = acc[mi][ni][0];
            dist[r0 * DPITCH + c0 + 1]       = acc[mi][ni][1];
            dist[(r0 + 8) * DPITCH + c0]     = acc[mi][ni][2];
            dist[(r0 + 8) * DPITCH + c0 + 1] = acc[mi][ni][3];
        }
    __syncthreads();

    // Approx top-6 per row: 2 threads/row scan 128 cols each, shfl pair-merge.
    // NOTE: snapshot candidates (ov/oi) BEFORE merging — insN mutates vs/is,
    // so shuffling vs[s] directly exchanges polluted values (R10 bug).
    {
        int r = tid >> 1, h = tid & 1, m = m0 + r;
        float vs[CPT]; int is[CPT];
        #pragma unroll
        for (int s = 0; s < CPT; s++) { vs[s] = 3.402823466e38f; is[s] = 0x7fffffff; }
        const float* dr = dist + r * DPITCH + h * 128;
        int nb = n0 + h * 128;
        #pragma unroll 4
        for (int j = 0; j < 128; j++) {
            float v = g_wsq[nb + j] - 2.0f * dr[j];
            insN(v, nb + j, vs, is, CPT);
        }
        float ov[CPT]; int oi[CPT];
        #pragma unroll
        for (int s = 0; s < CPT; s++) { ov[s] = vs[s]; oi[s] = is[s]; }
        #pragma unroll
        for (int s = 0; s < CPT; s++) {
            float pv = __shfl_xor_sync(0xffffffffu, ov[s], 1);
            int   pi = __shfl_xor_sync(0xffffffffu, oi[s], 1);
            insN(pv, pi, vs, is, CPT);
        }
        if (h == 0) {
            #pragma unroll
            for (int s = 0; s < CPT; s++) {
                g_cv[(size_t)(bx * CPT + s) * NN + m] = vs[s];
                g_ci[(size_t)(bx * CPT + s) * NN + m] = is[s];
            }
        }
    }
}

// ---------------------------------------------------------------------------
// Merge 8 tiles x 6 candidates -> global approx top-6 per row (coalesced)
__global__ void k_merge() {
    int m = blockIdx.x * 256 + threadIdx.x;
    float vs[6]; int is[6];
    #pragma unroll
    for (int s = 0; s < 6; s++) { vs[s] = 3.402823466e38f; is[s] = 0x7fffffff; }
    for (int c = 0; c < NCAND; c++)
        insN(g_cv[(size_t)c * NN + m], g_ci[(size_t)c * NN + m], vs, is, 6);
    #pragma unroll
    for (int s = 0; s < 6; s++) g_c6[(size_t)m * 6 + s] = is[s];
}

// ---------------------------------------------------------------------------
// Exact fp32 rescore (identical numerics to prior passing rounds) + counts/idx
__global__ void k_rescore(const float* __restrict__ W, float* __restrict__ out) {
    int wid = threadIdx.x >> 5, lane = threadIdx.x & 31;
    int m = blockIdx.x * 8 + wid;

    const float4* xp = reinterpret_cast<const float4*>(g_Xt + (size_t)m * DD);
    float4 xv[4];
    #pragma unroll
    for (int i = 0; i < 4; i++) xv[i] = xp[lane + 32 * i];

    float xs = g_xsq[m];
    float v0 = 3.402823466e38f, v1 = v0, v2 = v0;
    int   i0 = 0x7fffffff, i1 = i0, i2 = i0;

    for (int c = 0; c < 6; c++) {
        int idx = g_c6[(size_t)m * 6 + c];
        const float4* wp = reinterpret_cast<const float4*>(W + (size_t)idx * DD);
        float s = 0.f;
        #pragma unroll
        for (int i = 0; i < 4; i++) {
            float4 wv = wp[lane + 32 * i];
            s = fmaf(xv[i].x, wv.x, s);
            s = fmaf(xv[i].y, wv.y, s);
            s = fmaf(xv[i].z, wv.z, s);
            s = fmaf(xv[i].w, wv.w, s);
        }
        #pragma unroll
        for (int off = 16; off; off >>= 1) s += __shfl_down_sync(0xffffffffu, s, off);
        if (lane == 0) {
            float dist = __fadd_rn(__fadd_rn(xs, g_wsq[idx]), -2.0f * s);
            ins3(dist, idx, v0, i0, v1, i1, v2, i2);
        }
    }
    if (lane == 0) {
        g_top3[m * 3 + 0] = i0;
        g_top3[m * 3 + 1] = i1;
        g_top3[m * 3 + 2] = i2;
        atomicAdd(&g_counts[i0], 1);
        atomicAdd(&g_counts[i1], 1);
        atomicAdd(&g_counts[i2], 1);
        out[OUT_IDX_OFF + m] = (float)i2;
    }
}

// ---------------------------------------------------------------------------
// Fused quantize + transpose + loss: gathers W rows directly (L2/L1-resident),
// writes out[B,D,T] coalesced. Same value math/order as reference.
__global__ void k_out(const float* __restrict__ x, const float* __restrict__ W,
                      float* __restrict__ out) {
    __shared__ double red[8];
    int b  = blockIdx.z;
    int t0 = blockIdx.y * 32;
    int d0 = blockIdx.x * 32;
    int tx = threadIdx.x, ty = threadIdx.y;   // 32 x 8

    int m = b * TT + t0 + tx;
    int j0 = g_top3[m * 3 + 0];
    int j1 = g_top3[m * 3 + 1];
    int j2 = g_top3[m * 3 + 2];
    const float* w0 = W + (size_t)j0 * DD;
    const float* w1 = W + (size_t)j1 * DD;
    const float* w2 = W + (size_t)j2 * DD;

    float lsum = 0.f;
    #pragma unroll
    for (int i = 0; i < 4; i++) {
        int d = d0 + ty + 8 * i;
        float q = ((w0[d] + w1[d]) + w2[d]) / 3.0f;
        size_t off = (size_t)b * DD * TT + (size_t)d * TT + t0 + tx;
        float xv = x[off];
        out[OUT_Q_OFF + off] = q;
        float df = q - xv;
        lsum += df * df;
    }
    #pragma unroll
    for (int off = 16; off; off >>= 1)
        lsum += __shfl_down_sync(0xffffffffu, lsum, off);
    if (tx == 0) red[ty] = (double)lsum;
    __syncthreads();
    if (tx == 0 && ty == 0) {
        double s = 0.0;
        #pragma unroll
        for (int i = 0; i < 8; i++) s += red[i];
        atomicAdd(&g_loss_sum, s);
    }
}

// ---------------------------------------------------------------------------
__global__ void k_final(float* __restrict__ out) {
    __shared__ float red[256];
    int tid = threadIdx.x;
    float local = 0.f;
    for (int k = tid; k < KK; k += 256) {
        float p = (float)g_counts[k] / 16384.0f;
        local += p * logf(p + 1e-10f);
    }
    red[tid] = local;
    __syncthreads();
    #pragma unroll
    for (int s = 128; s; s >>= 1) {
        if (tid < s) red[tid] += red[tid + s];
        __syncthreads();
    }
    if (tid == 0) {
        out[OUT_PERP_OFF] = expf(-red[0]);
        float m = (float)(g_loss_sum / (double)((size_t)NN * DD));
        out[0] = m + 0.25f * m;
    }
}

// ---------------------------------------------------------------------------
extern "C" void kernel_launch(void* const* d_in, const int* in_sizes, int n_in,
                              void* d_out, int out_size) {
    const float* x = (const float*)d_in[0];
    const float* W = (const float*)d_in[1];
    if (n_in >= 2 && in_sizes[0] == KK * DD && in_sizes[1] == BB * DD * TT) {
        const float* tmp = x; x = W; W = tmp;
    }
    float* out = (float*)d_out;
    (void)out_size;

    cudaFuncSetAttribute(k_gemm, cudaFuncAttributeMaxDynamicSharedMemorySize,
                         SMEM_TOTAL);

    k_init   <<<8, 256>>>();
    k_prep   <<<320, 256>>>(x, W);
    k_split_w<<<(KK * DD) / 256, 256>>>(W);
    k_split_x<<<dim3(16, 8, 64), dim3(32, 8)>>>(x);
    k_gemm   <<<dim3(KK / BN, NN / BM), 256, SMEM_TOTAL>>>();
    k_merge  <<<64, 256>>>();
    k_rescore<<<2048, 256>>>(W, out);
    k_out    <<<dim3(16, 8, 64), dim3(32, 8)>>>(x, W, out);
    k_final  <<<1, 256>>>(out);
}